// round 15
// baseline (speedup 1.0000x reference)
#include <cuda_runtime.h>
#include <cuda_bf16.h>
#include <cuda_fp16.h>
#include <cstdint>
#include <cstddef>
#include <math.h>

// Problem constants
#define BATCH   2
#define SQ      2048
#define DMODEL  1024
#define NHEADS  16
#define DHID    4096
#define DKH     64
#define DVH     256
#define MROWS   (BATCH*SQ)   // 4096

typedef __half f16;

// ---------------- scratch (device globals; no allocation allowed) ----------
__device__ f16  g_xfh[MROWS * DMODEL];   // x fp16 hi
__device__ f16  g_xfl[MROWS * DMODEL];   // x fp16 lo
__device__ f16  g_Kf [MROWS * DMODEL];   // K fp16 single
__device__ f16  g_Vf [MROWS * DHID];     // V fp16 single
__device__ f16  g_Of [MROWS * DHID];     // gelu(attn) fp16 single
__device__ f16  g_Wkf[DMODEL * DMODEL];  // Wk^T fp16 single
__device__ f16  g_Wvf[DHID * DMODEL];    // Wv^T fp16 single
__device__ f16  g_Wff[DMODEL * DHID];    // Wf^T fp16 single

// ---------------- helpers ---------------------------------------------------
__device__ __forceinline__ void cp16(void* s, const void* g) {
    uint32_t sa = (uint32_t)__cvta_generic_to_shared(s);
    asm volatile("cp.async.cg.shared.global [%0], [%1], 16;\n" :: "r"(sa), "l"(g));
}
template<class T>
__device__ __forceinline__ uint32_t lds32(const T* p) {
    return *reinterpret_cast<const uint32_t*>(p);
}
__device__ __forceinline__ uint32_t packh2(float a, float b) {
    __half2 v = __floats2half2_rn(a, b);
    return *reinterpret_cast<uint32_t*>(&v);
}
__device__ __forceinline__ void mma_f16(float* c, uint32_t a0, uint32_t a1,
                                        uint32_t a2, uint32_t a3,
                                        uint32_t b0, uint32_t b1) {
    asm volatile(
        "mma.sync.aligned.m16n8k16.row.col.f32.f16.f16.f32 "
        "{%0,%1,%2,%3}, {%4,%5,%6,%7}, {%8,%9}, {%0,%1,%2,%3};\n"
        : "+f"(c[0]), "+f"(c[1]), "+f"(c[2]), "+f"(c[3])
        : "r"(a0), "r"(a1), "r"(a2), "r"(a3), "r"(b0), "r"(b1));
}
__device__ __forceinline__ void ldmx4(uint32_t& r0, uint32_t& r1,
                                      uint32_t& r2, uint32_t& r3, const void* p) {
    uint32_t a = (uint32_t)__cvta_generic_to_shared(p);
    asm volatile("ldmatrix.sync.aligned.m8n8.x4.shared.b16 {%0,%1,%2,%3}, [%4];"
                 : "=r"(r0), "=r"(r1), "=r"(r2), "=r"(r3) : "r"(a));
}
__device__ __forceinline__ void ldmx4t(uint32_t& r0, uint32_t& r1,
                                       uint32_t& r2, uint32_t& r3, const void* p) {
    uint32_t a = (uint32_t)__cvta_generic_to_shared(p);
    asm volatile("ldmatrix.sync.aligned.m8n8.x4.trans.shared.b16 {%0,%1,%2,%3}, [%4];"
                 : "=r"(r0), "=r"(r1), "=r"(r2), "=r"(r3) : "r"(a));
}
__device__ __forceinline__ float gelu_exact(float v) {
    return 0.5f * v * (1.0f + erff(v * 0.70710678118654752f));
}

// ---------------- conversion kernels ---------------------------------------
__global__ __launch_bounds__(256)
void convert_x_kernel(const float* __restrict__ src,
                      f16* __restrict__ fh, f16* __restrict__ fl, int n4)
{
    int i = blockIdx.x * blockDim.x + threadIdx.x;
    if (i >= n4) return;
    float4 v = ((const float4*)src)[i];
    f16 p0 = __float2half_rn(v.x), p1 = __float2half_rn(v.y);
    f16 p2 = __float2half_rn(v.z), p3 = __float2half_rn(v.w);
    __half2 h0 = __halves2half2(p0, p1), h1 = __halves2half2(p2, p3);
    ((uint32_t*)fh)[i*2+0] = *(uint32_t*)&h0;
    ((uint32_t*)fh)[i*2+1] = *(uint32_t*)&h1;
    ((uint32_t*)fl)[i*2+0] = packh2(v.x - __half2float(p0), v.y - __half2float(p1));
    ((uint32_t*)fl)[i*2+1] = packh2(v.z - __half2float(p2), v.w - __half2float(p3));
}

__global__ __launch_bounds__(256)
void transpose_f16_kernel(const float* __restrict__ W, f16* __restrict__ T,
                          int R, int C)
{
    __shared__ float tile[32][33];
    const int c0 = blockIdx.x * 32, r0 = blockIdx.y * 32;
    const int tx = threadIdx.x, ty = threadIdx.y;
    #pragma unroll
    for (int j = 0; j < 4; ++j)
        tile[ty + j*8][tx] = W[(size_t)(r0 + ty + j*8) * C + c0 + tx];
    __syncthreads();
    #pragma unroll
    for (int j = 0; j < 4; ++j)
        T[(size_t)(c0 + ty + j*8) * R + r0 + tx] = __float2half_rn(tile[tx][ty + j*8]);
}

// ---------------- GEMM tiling constants ------------------------------------
#define GBM 128
#define GBN 128
#define GBK 32
#define LDT 40
#define TBUF (GBM * LDT)
#define GEMM_SMEM_P  (6 * TBUF * (int)sizeof(f16))    // 61440 (A pair + B single)
#define GEMM_SMEM_F1 (4 * TBUF * (int)sizeof(f16))    // 40960 (A single + B single)

// ---- fp16 2-mma GEMM (K projection): A fp16 pair, B single, out fp16 single
__global__ __launch_bounds__(256)
void gemm_f16pair_kernel(const f16* __restrict__ Ah, const f16* __restrict__ Al,
                         const f16* __restrict__ B, const float* __restrict__ bias,
                         f16* __restrict__ C, int M, int N, int K)
{
    extern __shared__ f16 smp[];
    f16* sAh = smp;                 // [2][TBUF]
    f16* sAl = smp + 2 * TBUF;
    f16* sB  = smp + 4 * TBUF;

    const int t = threadIdx.x;
    const int warp = t >> 5, lane = t & 31;
    const int g = lane >> 2, tq = lane & 3;
    const int wm = warp >> 2, wn = warp & 3;
    const int m0 = wm * 64, n0 = wn * 32;
    const int rowBase = blockIdx.y * GBM, colBase = blockIdx.x * GBN;

    float acc[4][4][4];
    #pragma unroll
    for (int i = 0; i < 4; ++i)
        #pragma unroll
        for (int j = 0; j < 4; ++j)
            #pragma unroll
            for (int k = 0; k < 4; ++k) acc[i][j][k] = 0.f;

    auto load_tile = [&](int stage, int kt) {
        f16* dAh = sAh + stage * TBUF;
        f16* dAl = sAl + stage * TBUF;
        f16* dB  = sB  + stage * TBUF;
        #pragma unroll
        for (int it = 0; it < 2; ++it) {
            int c  = t + it * 256;
            int r  = c >> 2, cc = (c & 3) * 8;
            size_t ga = (size_t)(rowBase + r) * K + kt + cc;
            size_t gb = (size_t)(colBase + r) * K + kt + cc;
            cp16(dAh + r * LDT + cc, Ah + ga);
            cp16(dAl + r * LDT + cc, Al + ga);
            cp16(dB  + r * LDT + cc, B  + gb);
        }
    };

    const int nk = K / GBK;
    load_tile(0, 0);
    asm volatile("cp.async.commit_group;\n");

    for (int kt = 0; kt < nk; ++kt) {
        const int cur = kt & 1;
        if (kt + 1 < nk) load_tile(cur ^ 1, (kt + 1) * GBK);
        asm volatile("cp.async.commit_group;\n");
        asm volatile("cp.async.wait_group 1;\n");
        __syncthreads();

        const f16* Ahc = sAh + cur * TBUF;
        const f16* Alc = sAl + cur * TBUF;
        const f16* Bc  = sB  + cur * TBUF;

        #pragma unroll
        for (int ks = 0; ks < 2; ++ks) {
            uint32_t bf[4][2];
            #pragma unroll
            for (int ni = 0; ni < 4; ++ni) {
                const f16* p = Bc + (n0 + ni*8 + g) * LDT + ks*16 + tq*2;
                bf[ni][0] = lds32(p);  bf[ni][1] = lds32(p + 8);
            }
            #pragma unroll
            for (int mi = 0; mi < 4; ++mi) {
                const f16* pa = Ahc + (m0 + mi*16 + g) * LDT + ks*16 + tq*2;
                uint32_t ah0 = lds32(pa),     ah1 = lds32(pa + 8*LDT);
                uint32_t ah2 = lds32(pa + 8), ah3 = lds32(pa + 8*LDT + 8);
                const f16* pl = Alc + (m0 + mi*16 + g) * LDT + ks*16 + tq*2;
                uint32_t al0 = lds32(pl),     al1 = lds32(pl + 8*LDT);
                uint32_t al2 = lds32(pl + 8), al3 = lds32(pl + 8*LDT + 8);
                #pragma unroll
                for (int ni = 0; ni < 4; ++ni) {
                    mma_f16(acc[mi][ni], ah0, ah1, ah2, ah3, bf[ni][0], bf[ni][1]);
                    mma_f16(acc[mi][ni], al0, al1, al2, al3, bf[ni][0], bf[ni][1]);
                }
            }
        }
        __syncthreads();
    }

    #pragma unroll
    for (int mi = 0; mi < 4; ++mi) {
        #pragma unroll
        for (int ni = 0; ni < 4; ++ni) {
            int r0 = rowBase + m0 + mi*16 + g;
            int cb = colBase + n0 + ni*8 + tq*2;
            float b0 = bias[cb], b1 = bias[cb + 1];
            *(uint32_t*)&C[(size_t)r0 * N + cb] =
                packh2(acc[mi][ni][0] + b0, acc[mi][ni][1] + b1);
            *(uint32_t*)&C[(size_t)(r0+8) * N + cb] =
                packh2(acc[mi][ni][2] + b0, acc[mi][ni][3] + b1);
        }
    }
}

// ---- fp16 1-mma GEMM: C = A @ B^T + bias, both single fp16 ----------------
//  OUT==0: emit fp16 single.  OUT==1: emit fp32 with residual.
template<int OUT>
__global__ __launch_bounds__(256)
void gemm_f16_kernel(const f16* __restrict__ A, const f16* __restrict__ B,
                     const float* __restrict__ bias, const float* __restrict__ res,
                     f16* __restrict__ Cf, float* __restrict__ C32,
                     int M, int N, int K)
{
    extern __shared__ f16 smh[];
    f16* sA = smh;                 // [2][TBUF]
    f16* sB = smh + 2 * TBUF;      // [2][TBUF]

    const int t = threadIdx.x;
    const int warp = t >> 5, lane = t & 31;
    const int g = lane >> 2, tq = lane & 3;
    const int wm = warp >> 2, wn = warp & 3;
    const int m0 = wm * 64, n0 = wn * 32;
    const int rowBase = blockIdx.y * GBM, colBase = blockIdx.x * GBN;

    float acc[4][4][4];
    #pragma unroll
    for (int i = 0; i < 4; ++i)
        #pragma unroll
        for (int j = 0; j < 4; ++j)
            #pragma unroll
            for (int k = 0; k < 4; ++k) acc[i][j][k] = 0.f;

    auto load_tile = [&](int stage, int kt) {
        f16* dA = sA + stage * TBUF;
        f16* dB = sB + stage * TBUF;
        #pragma unroll
        for (int it = 0; it < 2; ++it) {
            int c  = t + it * 256;
            int r  = c >> 2, cc = (c & 3) * 8;
            cp16(dA + r * LDT + cc, A + (size_t)(rowBase + r) * K + kt + cc);
            cp16(dB + r * LDT + cc, B + (size_t)(colBase + r) * K + kt + cc);
        }
    };

    const int nk = K / GBK;
    load_tile(0, 0);
    asm volatile("cp.async.commit_group;\n");

    for (int kt = 0; kt < nk; ++kt) {
        const int cur = kt & 1;
        if (kt + 1 < nk) load_tile(cur ^ 1, (kt + 1) * GBK);
        asm volatile("cp.async.commit_group;\n");
        asm volatile("cp.async.wait_group 1;\n");
        __syncthreads();

        const f16* Ac = sA + cur * TBUF;
        const f16* Bc = sB + cur * TBUF;

        #pragma unroll
        for (int ks = 0; ks < 2; ++ks) {
            uint32_t bf[4][2];
            #pragma unroll
            for (int ni = 0; ni < 4; ++ni) {
                const f16* p = Bc + (n0 + ni*8 + g) * LDT + ks*16 + tq*2;
                bf[ni][0] = lds32(p);  bf[ni][1] = lds32(p + 8);
            }
            #pragma unroll
            for (int mi = 0; mi < 4; ++mi) {
                const f16* pa = Ac + (m0 + mi*16 + g) * LDT + ks*16 + tq*2;
                uint32_t a0 = lds32(pa),     a1 = lds32(pa + 8*LDT);
                uint32_t a2 = lds32(pa + 8), a3 = lds32(pa + 8*LDT + 8);
                #pragma unroll
                for (int ni = 0; ni < 4; ++ni)
                    mma_f16(acc[mi][ni], a0, a1, a2, a3, bf[ni][0], bf[ni][1]);
            }
        }
        __syncthreads();
    }

    #pragma unroll
    for (int mi = 0; mi < 4; ++mi) {
        #pragma unroll
        for (int ni = 0; ni < 4; ++ni) {
            int r0 = rowBase + m0 + mi*16 + g;
            int cb = colBase + n0 + ni*8 + tq*2;
            float b0 = bias[cb], b1 = bias[cb + 1];
            float v0 = acc[mi][ni][0] + b0, v1 = acc[mi][ni][1] + b1;
            float v2 = acc[mi][ni][2] + b0, v3 = acc[mi][ni][3] + b1;
            if (OUT == 0) {
                *(uint32_t*)&Cf[(size_t)r0 * N + cb]     = packh2(v0, v1);
                *(uint32_t*)&Cf[(size_t)(r0+8) * N + cb] = packh2(v2, v3);
            } else {
                float2 r0v = *(const float2*)&res[(size_t)r0 * N + cb];
                float2 r1v = *(const float2*)&res[(size_t)(r0+8) * N + cb];
                float2 o0 = { v0 + r0v.x, v1 + r0v.y };
                float2 o1 = { v2 + r1v.x, v3 + r1v.y };
                *(float2*)&C32[(size_t)r0 * N + cb]     = o0;
                *(float2*)&C32[(size_t)(r0+8) * N + cb] = o1;
            }
        }
    }
}

// ---------------- tensor-core causal flash attention + GELU ----------------
// AQT=64, 128 threads (4 warps x 16 rows), 2 CTAs/SM.
#define AQT 64
#define AKT 64
#define LDQ 72
#define LDK 72
#define LDV 264
#define QBUF (AQT*LDQ)                 // 4608
#define KBUF (AKT*LDK)                 // 4608
#define VBUF (AKT*LDV)                 // 16896
#define ATTN_SMEM ((2*QBUF + 2*KBUF + 2*VBUF) * 2)    // 104448 B

__global__ __launch_bounds__(128, 2)
void attn_mma_kernel(const f16* __restrict__ xh, const f16* __restrict__ xl,
                     const f16* __restrict__ Kf, const f16* __restrict__ Vf,
                     f16* __restrict__ Og)
{
    extern __shared__ char smraw[];
    f16* sQh = (f16*)smraw;
    f16* sQl = sQh + QBUF;
    f16* sK  = sQl + QBUF;        // [2][KBUF]
    f16* sV  = sK + 2*KBUF;       // [2][VBUF]

    const int qtile = gridDim.x - 1 - blockIdx.x;   // long CTAs first
    const int bh = blockIdx.y;
    const int b = bh >> 4, h = bh & 15;
    const int q0 = qtile * AQT;
    const int t = threadIdx.x, warp = t >> 5, lane = t & 31;
    const int g = lane >> 2, tq = lane & 3;
    const int wrow = warp * 16;

    // ---- Q tile load (once): 64 rows x 64 cols x 2 planes ----
    const size_t qbase = (size_t)(b*SQ + q0) * DMODEL + (size_t)h * DKH;
    #pragma unroll
    for (int i = 0; i < 8; ++i) {
        int chunk = t + i*128;              // 0..1023
        int r = chunk >> 4;                 // 0..63
        int rem = chunk & 15;
        const f16* src = (rem & 8) ? xl : xh;
        f16* dst = (rem & 8) ? sQl : sQh;
        int c = (rem & 7) * 8;
        cp16(dst + r*LDQ + c, src + qbase + (size_t)r*DMODEL + c);
    }

    const size_t kbase = (size_t)(b*SQ) * DMODEL + (size_t)h * DKH;
    const size_t vbase = (size_t)(b*SQ) * DHID  + (size_t)h * DVH;

    auto load_kv = [&](int st, int kb) {
        f16* dK = sK + st*KBUF;
        f16* dV = sV + st*VBUF;
        #pragma unroll
        for (int i = 0; i < 4; ++i) {
            int chunk = t + i*128;          // 0..511
            int r = chunk >> 3;             // 0..63
            int c = (chunk & 7) * 8;
            cp16(dK + r*LDK + c, Kf + kbase + (size_t)(kb + r)*DMODEL + c);
        }
        #pragma unroll
        for (int i = 0; i < 16; ++i) {
            int chunk = t + i*128;          // 0..2047
            int r = chunk >> 5;             // 0..63
            int c = (chunk & 31) * 8;
            cp16(dV + r*LDV + c, Vf + vbase + (size_t)(kb + r)*DHID + c);
        }
    };

    float acc[32][4];
    #pragma unroll
    for (int i = 0; i < 32; ++i) { acc[i][0]=0.f; acc[i][1]=0.f; acc[i][2]=0.f; acc[i][3]=0.f; }
    float m0 = -INFINITY, m1 = -INFINITY, l0 = 0.f, l1 = 0.f;

    const int ntiles = qtile + 1;
    load_kv(0, 0);
    asm volatile("cp.async.commit_group;\n");

    // ldmatrix per-lane bases
    const int lr = lane & 7;
    // A-fragment (Q): matrices [m0-7,k0-7],[m8-15,k0-7],[m0-7,k8-15],[m8-15,k8-15]
    const int qa_row = wrow + lr + ((lane & 8) ? 8 : 0);
    const int qa_col = (lane & 16) ? 8 : 0;
    const f16* qah = sQh + qa_row * LDQ + qa_col;
    const f16* qal = sQl + qa_row * LDQ + qa_col;
    // B-fragment (K), x4 covers two n-tiles: lanes0-7 ntEven k0, 8-15 ntEven k8,
    //                                        16-23 ntOdd k0, 24-31 ntOdd k8
    const int kb_row = ((lane & 16) ? 8 : 0) + lr;   // row within the nt-pair (16 rows)
    const int kb_col = (lane & 8) ? 8 : 0;
    // V ldmatrix (trans) offset
    const int mat = lane >> 3;
    const int lmoff = ((mat & 1)*8 + (lane & 7)) * LDV + (mat >> 1)*8;

    const int qrow0 = q0 + wrow + g;
    const int qrow1 = qrow0 + 8;

    for (int j = 0; j < ntiles; ++j) {
        const int cur = j & 1;
        const int kb = j * AKT;
        if (j + 1 < ntiles) load_kv(cur ^ 1, kb + AKT);
        asm volatile("cp.async.commit_group;\n");
        asm volatile("cp.async.wait_group 1;\n");
        __syncthreads();

        {
            const f16* cK = sK + cur*KBUF;
            const f16* cV = sV + cur*VBUF;

            // ---- S = Q @ K^T (Q fp16 hi/lo pair, K single: 2-mma, ldmatrix) --
            float sc[8][4];
            #pragma unroll
            for (int nt = 0; nt < 8; ++nt) { sc[nt][0]=0.f; sc[nt][1]=0.f; sc[nt][2]=0.f; sc[nt][3]=0.f; }
            #pragma unroll
            for (int ks = 0; ks < 4; ++ks) {
                uint32_t qh0,qh1,qh2,qh3, ql0,ql1,ql2,ql3;
                ldmx4(qh0,qh1,qh2,qh3, qah + ks*16);
                ldmx4(ql0,ql1,ql2,ql3, qal + ks*16);
                #pragma unroll
                for (int ntp = 0; ntp < 4; ++ntp) {
                    uint32_t k0,k1,k2,k3;
                    ldmx4(k0,k1,k2,k3,
                          cK + (ntp*16 + kb_row)*LDK + ks*16 + kb_col);
                    mma_f16(sc[2*ntp],   qh0,qh1,qh2,qh3, k0, k1);
                    mma_f16(sc[2*ntp],   ql0,ql1,ql2,ql3, k0, k1);
                    mma_f16(sc[2*ntp+1], qh0,qh1,qh2,qh3, k2, k3);
                    mma_f16(sc[2*ntp+1], ql0,ql1,ql2,ql3, k2, k3);
                }
            }

            // ---- causal mask (diagonal tile only) ----
            if (kb + AKT - 1 > q0 + wrow) {
                #pragma unroll
                for (int nt = 0; nt < 8; ++nt) {
                    int k0i = kb + nt*8 + tq*2;
                    if (k0i     > qrow0) sc[nt][0] = -INFINITY;
                    if (k0i + 1 > qrow0) sc[nt][1] = -INFINITY;
                    if (k0i     > qrow1) sc[nt][2] = -INFINITY;
                    if (k0i + 1 > qrow1) sc[nt][3] = -INFINITY;
                }
            }

            // ---- online softmax ----
            float mx0 = -INFINITY, mx1 = -INFINITY;
            #pragma unroll
            for (int nt = 0; nt < 8; ++nt) {
                mx0 = fmaxf(mx0, fmaxf(sc[nt][0], sc[nt][1]));
                mx1 = fmaxf(mx1, fmaxf(sc[nt][2], sc[nt][3]));
            }
            mx0 = fmaxf(mx0, __shfl_xor_sync(0xffffffffu, mx0, 1));
            mx0 = fmaxf(mx0, __shfl_xor_sync(0xffffffffu, mx0, 2));
            mx1 = fmaxf(mx1, __shfl_xor_sync(0xffffffffu, mx1, 1));
            mx1 = fmaxf(mx1, __shfl_xor_sync(0xffffffffu, mx1, 2));
            float mn0 = fmaxf(m0, mx0), mn1 = fmaxf(m1, mx1);
            float al0 = __expf(m0 - mn0), al1 = __expf(m1 - mn1);
            m0 = mn0; m1 = mn1;

            float ps0 = 0.f, ps1 = 0.f;
            uint32_t ph[8][2];
            #pragma unroll
            for (int nt = 0; nt < 8; ++nt) {
                float p0 = __expf(sc[nt][0] - mn0);
                float p1 = __expf(sc[nt][1] - mn0);
                float p2 = __expf(sc[nt][2] - mn1);
                float p3 = __expf(sc[nt][3] - mn1);
                ps0 += p0 + p1; ps1 += p2 + p3;
                ph[nt][0] = packh2(p0, p1);
                ph[nt][1] = packh2(p2, p3);
            }
            ps0 += __shfl_xor_sync(0xffffffffu, ps0, 1);
            ps0 += __shfl_xor_sync(0xffffffffu, ps0, 2);
            ps1 += __shfl_xor_sync(0xffffffffu, ps1, 1);
            ps1 += __shfl_xor_sync(0xffffffffu, ps1, 2);
            l0 = l0*al0 + ps0;
            l1 = l1*al1 + ps1;

            // ---- rescale accumulators only when the max actually moved ----
            if (__any_sync(0xffffffffu, (al0 != 1.f) || (al1 != 1.f))) {
                #pragma unroll
                for (int i = 0; i < 32; ++i) {
                    acc[i][0] *= al0; acc[i][1] *= al0;
                    acc[i][2] *= al1; acc[i][3] *= al1;
                }
            }

            // ---- O += P @ V  (fp16 single) ----
            #pragma unroll
            for (int kk = 0; kk < 4; ++kk) {
                uint32_t a0 = ph[2*kk][0],   a1 = ph[2*kk][1];
                uint32_t a2 = ph[2*kk+1][0], a3 = ph[2*kk+1][1];
                #pragma unroll
                for (int ng = 0; ng < 16; ++ng) {
                    uint32_t v0,v1,v2,v3;
                    ldmx4t(v0,v1,v2,v3, cV + kk*16*LDV + ng*16 + lmoff);
                    mma_f16(acc[2*ng],   a0,a1,a2,a3, v0, v1);
                    mma_f16(acc[2*ng+1], a0,a1,a2,a3, v2, v3);
                }
            }
        }
        __syncthreads();
    }

    // ---- epilogue: normalize + GELU -> fp16 single ----
    const float inv0 = 1.0f / l0, inv1 = 1.0f / l1;
    f16* o0p = Og + ((size_t)b*SQ + qrow0)*DHID + (size_t)h*DVH;
    f16* o1p = Og + ((size_t)b*SQ + qrow1)*DHID + (size_t)h*DVH;
    #pragma unroll
    for (int nt = 0; nt < 32; ++nt) {
        int c = nt*8 + tq*2;
        float v0 = gelu_exact(acc[nt][0] * inv0);
        float v1 = gelu_exact(acc[nt][1] * inv0);
        float v2 = gelu_exact(acc[nt][2] * inv1);
        float v3 = gelu_exact(acc[nt][3] * inv1);
        *(uint32_t*)(o0p + c) = packh2(v0, v1);
        *(uint32_t*)(o1p + c) = packh2(v2, v3);
    }
}

// ---------------------------------------------------------------------------
extern "C" void kernel_launch(void* const* d_in, const int* in_sizes, int n_in,
                              void* d_out, int out_size)
{
    const float* x  = (const float*)d_in[0];
    const float* Wk = (const float*)d_in[1];
    const float* bk = (const float*)d_in[2];
    const float* Wv = (const float*)d_in[3];
    const float* bv = (const float*)d_in[4];
    const float* Wf = (const float*)d_in[5];
    const float* bf_ = (const float*)d_in[6];
    float* out = (float*)d_out;

    f16 *gxfh, *gxfl, *gKf, *gVf, *gOf, *gWkf, *gWvf, *gWff;
    cudaGetSymbolAddress((void**)&gxfh, g_xfh);
    cudaGetSymbolAddress((void**)&gxfl, g_xfl);
    cudaGetSymbolAddress((void**)&gKf,  g_Kf);
    cudaGetSymbolAddress((void**)&gVf,  g_Vf);
    cudaGetSymbolAddress((void**)&gOf,  g_Of);
    cudaGetSymbolAddress((void**)&gWkf, g_Wkf);
    cudaGetSymbolAddress((void**)&gWvf, g_Wvf);
    cudaGetSymbolAddress((void**)&gWff, g_Wff);

    cudaFuncSetAttribute(attn_mma_kernel,
        cudaFuncAttributeMaxDynamicSharedMemorySize, ATTN_SMEM);
    cudaFuncSetAttribute(gemm_f16pair_kernel,
        cudaFuncAttributeMaxDynamicSharedMemorySize, GEMM_SMEM_P);
    cudaFuncSetAttribute(gemm_f16_kernel<0>,
        cudaFuncAttributeMaxDynamicSharedMemorySize, GEMM_SMEM_F1);
    cudaFuncSetAttribute(gemm_f16_kernel<1>,
        cudaFuncAttributeMaxDynamicSharedMemorySize, GEMM_SMEM_F1);

    // 0) conversions
    convert_x_kernel<<<(MROWS*DMODEL/4 + 255)/256, 256>>>(
        x, gxfh, gxfl, MROWS*DMODEL/4);
    transpose_f16_kernel<<<dim3(DMODEL/32, DMODEL/32), dim3(32,8)>>>(
        Wk, gWkf, DMODEL, DMODEL);
    transpose_f16_kernel<<<dim3(DHID/32,   DMODEL/32), dim3(32,8)>>>(
        Wv, gWvf, DMODEL, DHID);
    transpose_f16_kernel<<<dim3(DMODEL/32, DHID/32),   dim3(32,8)>>>(
        Wf, gWff, DHID, DMODEL);

    // 1) K = x @ Wk + bk  -> fp16 single  (fp16 2-mma, x pair)
    gemm_f16pair_kernel<<<dim3(DMODEL/GBN, MROWS/GBM), 256, GEMM_SMEM_P>>>(
        gxfh, gxfl, gWkf, bk, gKf, MROWS, DMODEL, DMODEL);

    // 2) V = x @ Wv + bv  -> fp16 single  (fp16 1-mma)
    gemm_f16_kernel<0><<<dim3(DHID/GBN, MROWS/GBM), 256, GEMM_SMEM_F1>>>(
        gxfh, gWvf, bv, nullptr, gVf, nullptr, MROWS, DHID, DMODEL);

    // 3) gelu(attn(x,K,V)) -> fp16 single  (AQT=64, 2 CTAs/SM, ldmatrix)
    attn_mma_kernel<<<dim3(SQ/AQT, BATCH*NHEADS), 128, ATTN_SMEM>>>(
        gxfh, gxfl, gKf, gVf, gOf);

    // 4) out = x + O @ Wf + bf  (fp16 1-mma)
    gemm_f16_kernel<1><<<dim3(DMODEL/GBN, MROWS/GBM), 256, GEMM_SMEM_F1>>>(
        gOf, gWff, bf_, x, nullptr, out, MROWS, DMODEL, DHID);
}